// round 3
// baseline (speedup 1.0000x reference)
#include <cuda_runtime.h>

#define V_NODES 2048
#define D_F     128
#define NBLK    128           // scatter blocks
#define NPB     16            // nodes per scatter block (V_NODES / NBLK)
#define NK      73            // 1 + 8 + 64 output coefficient rows

// Scratch (static device globals — no allocation allowed)
__device__ float g_deg[V_NODES];
__device__ float g_partial[NBLK * NK * D_F];   // block-major partials

// ---------------------------------------------------------------------------
// Kernel 1: row sums of W -> deg[row]
// ---------------------------------------------------------------------------
__global__ void __launch_bounds__(256) deg_kernel(const float* __restrict__ W) {
    const int row = blockIdx.x;
    const float4* w4 = (const float4*)(W + (size_t)row * V_NODES);
    float s = 0.f;
#pragma unroll
    for (int i = 0; i < 2; i++) {
        float4 v = w4[threadIdx.x + i * 256];
        s += (v.x + v.y) + (v.z + v.w);
    }
#pragma unroll
    for (int off = 16; off; off >>= 1)
        s += __shfl_down_sync(0xffffffffu, s, off);

    __shared__ float ws[8];
    if ((threadIdx.x & 31) == 0) ws[threadIdx.x >> 5] = s;
    __syncthreads();
    if (threadIdx.x < 8) {
        float t = ws[threadIdx.x];
#pragma unroll
        for (int off = 4; off; off >>= 1)
            t += __shfl_down_sync(0xffu, t, off);
        if (threadIdx.x == 0) g_deg[row] = t;
    }
}

// ---------------------------------------------------------------------------
// Kernel 2: per-node filter responses + scattering partial sums.
// Block b handles nodes [b*16, b*16+16), thread = feature index d (128).
// acc layout: k=0 -> mean(f); k=1..8 -> lam_j * |f|; k=9+8*j1+j2 -> lam_j1*lam_j2*|f|
// This matches the reference output flattening: out[k*128 + d].
// ---------------------------------------------------------------------------
__global__ void __launch_bounds__(128) scat_kernel(const float* __restrict__ f) {
    __shared__ float lam_s[8][NPB];
    const int b = blockIdx.x;
    const int tid = threadIdx.x;

    if (tid < NPB) {
        const int a = b * NPB + tid;
        float dg = g_deg[a];
        float inv = 1.0f / fmaxf(1.0f, dg);       // dhalf^2 with clamp
        float E = fabsf(dg * inv);                // |eigenvalue| for this node
        float logE = logf(E);
        const float Ac = 0.34657359027997264f;    // A = 3*ln(2)/6
        float s = 1.125f;                         // (R/2)*sum(d^2) + (R/2)*d0^2
#pragma unroll
        for (int j = 2; j <= 8; j++) {
            float x = logE - Ac * (float)(j - 1) * (1.0f / 3.0f);
            float w = 0.0f;
            if (x > -Ac && x <= 0.0f)
                w = 0.5f - 0.5f * cosf(x * (6.283185307179586f / Ac));
            lam_s[j - 1][tid] = w;
            s -= w * w;
        }
        lam_s[0][tid] = sqrtf(fmaxf(s, 0.0f));    // scaling function
    }
    __syncthreads();

    // Prefetch this block's f tile (16 nodes x 1 feature per thread) for MLP.
    float fv[NPB];
#pragma unroll
    for (int n = 0; n < NPB; n++)
        fv[n] = f[(size_t)(b * NPB + n) * D_F + tid];

    float acc[NK];
#pragma unroll
    for (int k = 0; k < NK; k++) acc[k] = 0.f;

#pragma unroll 4
    for (int n = 0; n < NPB; n++) {
        float v = fv[n];
        float af = fabsf(v);
        acc[0] += v;
        float l[8];
#pragma unroll
        for (int j = 0; j < 8; j++) l[j] = lam_s[j][n];   // smem broadcast
#pragma unroll
        for (int j = 0; j < 8; j++) acc[1 + j] += l[j] * af;
#pragma unroll
        for (int j1 = 0; j1 < 8; j1++) {
            float t = l[j1] * af;
#pragma unroll
            for (int j2 = 0; j2 < 8; j2++)
                acc[9 + j1 * 8 + j2] += l[j2] * t;
        }
    }

    float* p = g_partial + (size_t)b * (NK * D_F) + tid;
#pragma unroll
    for (int k = 0; k < NK; k++)
        p[k * D_F] = acc[k];
}

// ---------------------------------------------------------------------------
// Kernel 3: sum partials over the 128 scatter blocks, scale by 1/V.
// Coalesced: consecutive threads read consecutive addresses each iteration.
// ---------------------------------------------------------------------------
__global__ void __launch_bounds__(256) reduce_kernel(float* __restrict__ out) {
    const int i = blockIdx.x * 256 + threadIdx.x;
    if (i >= NK * D_F) return;
    float s0 = 0.f, s1 = 0.f, s2 = 0.f, s3 = 0.f;
#pragma unroll
    for (int b = 0; b < NBLK; b += 4) {
        s0 += g_partial[(b + 0) * (NK * D_F) + i];
        s1 += g_partial[(b + 1) * (NK * D_F) + i];
        s2 += g_partial[(b + 2) * (NK * D_F) + i];
        s3 += g_partial[(b + 3) * (NK * D_F) + i];
    }
    out[i] = ((s0 + s1) + (s2 + s3)) * (1.0f / (float)V_NODES);
}

// ---------------------------------------------------------------------------
extern "C" void kernel_launch(void* const* d_in, const int* in_sizes, int n_in,
                              void* d_out, int out_size) {
    const float* W = (const float*)d_in[0];
    const float* f = (const float*)d_in[1];
    float* out = (float*)d_out;

    deg_kernel<<<V_NODES, 256>>>(W);
    scat_kernel<<<NBLK, 128>>>(f);
    reduce_kernel<<<(NK * D_F + 255) / 256, 256>>>(out);
}